// round 5
// baseline (speedup 1.0000x reference)
#include <cuda_runtime.h>

// 7-level db4 DWT -> soft threshold -> IDWT, fully fused in SMEM.
// One CTA per row; dense vector LDS/LDG as in R4; inner filter math uses
// packed fma.rn.f32x2 (FFMA2) with horizontal-add reduction.

#define NTHREADS 128
#define NROWS    32768
#define N0       1116

// db4 filters
#define L0c (-0.010597401784997278f)
#define L1c ( 0.032883011666982945f)
#define L2c ( 0.030841381835986965f)
#define L3c (-0.18703481171888114f)
#define L4c (-0.02798376941698385f)
#define L5c ( 0.6308807679295904f)
#define L6c ( 0.7148465705525415f)
#define L7c ( 0.23037781330885523f)
// DEC_HI[i] = (-1)^(i+1) * DEC_LO[7-i]
#define H0c (-L7c)
#define H1c ( L6c)
#define H2c (-L5c)
#define H3c ( L4c)
#define H4c (-L3c)
#define H5c ( L2c)
#define H6c (-L1c)
#define H7c ( L0c)

__device__ __forceinline__ float2 fma2(float2 a, float2 b, float2 c) {
    unsigned long long ua = reinterpret_cast<unsigned long long&>(a);
    unsigned long long ub = reinterpret_cast<unsigned long long&>(b);
    unsigned long long uc = reinterpret_cast<unsigned long long&>(c);
    unsigned long long ud;
    asm("fma.rn.f32x2 %0, %1, %2, %3;" : "=l"(ud) : "l"(ua), "l"(ub), "l"(uc));
    return reinterpret_cast<float2&>(ud);
}
__device__ __forceinline__ float2 fmul2(float2 a, float2 b) {
    unsigned long long ua = reinterpret_cast<unsigned long long&>(a);
    unsigned long long ub = reinterpret_cast<unsigned long long&>(b);
    unsigned long long ud;
    asm("mul.rn.f32x2 %0, %1, %2;" : "=l"(ud) : "l"(ua), "l"(ub));
    return reinterpret_cast<float2&>(ud);
}

__device__ __forceinline__ float softf(float c, float t) {
    return copysignf(fmaxf(fabsf(c) - t, 0.0f), c);
}

// Horizontal db4 analysis dot-products over r[0..8) (as 4 float2 pairs).
// ca = sum r[k]*DLO[7-k]; cd = sum r[k]*DHI[7-k].
__device__ __forceinline__ void fwd_dot(const float* r, float& ca, float& cd) {
    const float2 p0 = *(const float2*)(r);
    const float2 p1 = *(const float2*)(r + 2);
    const float2 p2 = *(const float2*)(r + 4);
    const float2 p3 = *(const float2*)(r + 6);
    float2 a = fmul2(p0, make_float2(L7c, L6c));
    a = fma2(p1, make_float2(L5c, L4c), a);
    a = fma2(p2, make_float2(L3c, L2c), a);
    a = fma2(p3, make_float2(L1c, L0c), a);
    float2 d = fmul2(p0, make_float2(H7c, H6c));
    d = fma2(p1, make_float2(H5c, H4c), d);
    d = fma2(p2, make_float2(H3c, H2c), d);
    d = fma2(p3, make_float2(H1c, H0c), d);
    ca = a.x + a.y;
    cd = d.x + d.y;
}

// ---- forward level 1: read row directly from gmem (zero-extended).
template<int NTH>
__device__ __forceinline__ void fwd_gmem(const float* __restrict__ x,
                                         float* __restrict__ an,
                                         float* __restrict__ dph,
                                         float thr, int tid)
{
    constexpr int M   = 561;
    constexpr int PAD = (M + 1) / 2 + 8;   // 289
    for (int t = tid; t < PAD; t += NTH) {
        float r[16];
        const int b0 = 4 * t - 8;
        #pragma unroll
        for (int bi = 0; bi < 4; bi++) {
            const int idx = b0 + 4 * bi;
            float4 v = make_float4(0.f, 0.f, 0.f, 0.f);
            if (idx >= 0 && idx + 4 <= N0) v = *(const float4*)(x + idx);
            *(float4*)(r + 4 * bi) = v;
        }
        float ca0, cd0, ca1, cd1;
        fwd_dot(r + 2, ca0, cd0);
        fwd_dot(r + 4, ca1, cd1);
        cd0 = softf(cd0, thr); cd1 = softf(cd1, thr);
        const int j0 = 2 * t;
        *(float2*)(an + 6 + j0) = make_float2(j0 < M ? ca0 : 0.f,
                                              (j0 + 1) < M ? ca1 : 0.f);
        if (j0 < M)
            *(float2*)(dph + j0) = make_float2(cd0, (j0 + 1) < M ? cd1 : 0.f);
    }
}

// ---- forward SMEM level, 2 outputs/unit, dense 16B-stride LDS.128.
template<int M, bool LAST, int NTH>
__device__ __forceinline__ void fwd_level(const float* __restrict__ a,
                                          float* __restrict__ an,
                                          float* __restrict__ dph,
                                          float thr, int tid)
{
    constexpr int PAD = (M + 1) / 2 + 8;
    for (int t = tid; t < PAD; t += NTH) {
        float r[12];
        *(float4*)(r)     = *(const float4*)(a + 4 * t);
        *(float4*)(r + 4) = *(const float4*)(a + 4 * t + 4);
        *(float4*)(r + 8) = *(const float4*)(a + 4 * t + 8);
        float ca0, cd0, ca1, cd1;
        fwd_dot(r,     ca0, cd0);
        fwd_dot(r + 2, ca1, cd1);
        cd0 = softf(cd0, thr); cd1 = softf(cd1, thr);
        if (LAST) { ca0 = softf(ca0, thr); ca1 = softf(ca1, thr); }
        const int j0 = 2 * t;
        *(float2*)(an + 6 + j0) = make_float2(j0 < M ? ca0 : 0.f,
                                              (j0 + 1) < M ? ca1 : 0.f);
        if (j0 < M)
            *(float2*)(dph + j0) = make_float2(cd0, (j0 + 1) < M ? cd1 : 0.f);
    }
}

// ---- inverse level, 4 outputs/unit, packed-pair math; o may be gmem.
template<int MD, int NTH>
__device__ __forceinline__ void inv_level(const float* __restrict__ a,
                                          const float* __restrict__ d,
                                          float* __restrict__ o, int tid)
{
    constexpr int OLEN  = 2 * MD - 6;
    constexpr int QUADS = (OLEN + 3) / 4;
    for (int u = tid; u < QUADS; u += NTH) {
        const int s = 2 * u;
        const float2 a01 = *(const float2*)(a + s);
        const float2 a23 = *(const float2*)(a + s + 2);
        const float  a4  = a[s + 4];
        const float2 d01 = *(const float2*)(d + s);
        const float2 d23 = *(const float2*)(d + s + 2);
        const float  d4  = d[s + 4];

        // o0 = a01.(L1,L3) + a23.(L5,L7) + d01.(H1,H3) + d23.(H5,H7)
        float2 acc0 = fmul2(d23, make_float2(H5c, H7c));
        acc0 = fma2(d01, make_float2(H1c, H3c), acc0);
        acc0 = fma2(a23, make_float2(L5c, L7c), acc0);
        acc0 = fma2(a01, make_float2(L1c, L3c), acc0);
        const float o0 = acc0.x + acc0.y;

        // o1 = a01.(L0,L2) + a23.(L4,L6) + d01.(H0,H2) + d23.(H4,H6)
        float2 acc1 = fmul2(d23, make_float2(H4c, H6c));
        acc1 = fma2(d01, make_float2(H0c, H2c), acc1);
        acc1 = fma2(a23, make_float2(L4c, L6c), acc1);
        acc1 = fma2(a01, make_float2(L0c, L2c), acc1);
        const float o1 = acc1.x + acc1.y;

        // o2 = a1*L1 + a23.(L3,L5) + a4*L7 + d1*H1 + d23.(H3,H5) + d4*H7
        float2 acc2 = fmul2(d23, make_float2(H3c, H5c));
        acc2 = fma2(a23, make_float2(L3c, L5c), acc2);
        float o2 = acc2.x + acc2.y;
        o2 = fmaf(a01.y, L1c, o2);
        o2 = fmaf(a4,    L7c, o2);
        o2 = fmaf(d01.y, H1c, o2);
        o2 = fmaf(d4,    H7c, o2);

        // o3 = a1*L0 + a23.(L2,L4) + a4*L6 + d1*H0 + d23.(H2,H4) + d4*H6
        float2 acc3 = fmul2(d23, make_float2(H2c, H4c));
        acc3 = fma2(a23, make_float2(L2c, L4c), acc3);
        float o3 = acc3.x + acc3.y;
        o3 = fmaf(a01.y, L0c, o3);
        o3 = fmaf(a4,    L6c, o3);
        o3 = fmaf(d01.y, H0c, o3);
        o3 = fmaf(d4,    H6c, o3);

        if (4 * u + 3 < OLEN) *(float4*)(o + 4 * u) = make_float4(o0, o1, o2, o3);
        else                  *(float2*)(o + 4 * u) = make_float2(o0, o1);
    }
}

__global__ __launch_bounds__(NTHREADS)
void wavelet_fused_kernel(const float* __restrict__ x,
                          const float* __restrict__ rawthr,
                          float* __restrict__ out)
{
    // Level lengths: {1116, 561, 284, 145, 76, 41, 24, 15}
    __shared__ __align__(16) float sA[1168];
    __shared__ __align__(16) float sB[640];
    __shared__ __align__(16) float sD[1152];  // doff: 0,562,846,992,1068,1110,1134

    const int row = blockIdx.x;
    const int tid = threadIdx.x;
    const float thr = fmaxf(__ldg(rawthr), 0.01f);
    const float* __restrict__ xr = x + (size_t)row * N0;

    // residual zero-fill (regions never overwritten before their reads)
    if (tid < 6)       { sA[tid] = 0.f; sB[tid] = 0.f; }
    if (tid >= 64 && tid < 64 + 56) sB[520 + tid] = 0.f;   // sB[584..640)
    __syncthreads();

    // ---- forward DWT (level 1 straight from gmem)
    fwd_gmem<NTHREADS>(xr, sB, sD + 0, thr, tid);                 __syncthreads();
    fwd_level<284, false, NTHREADS>(sB, sA, sD + 562, thr, tid);  __syncthreads();
    fwd_level<145, false, NTHREADS>(sA, sB, sD + 846, thr, tid);  __syncthreads();
    fwd_level<76,  false, NTHREADS>(sB, sA, sD + 992, thr, tid);  __syncthreads();

    // ---- tiny levels: single warp, __syncwarp only
    if (tid < 32) {
        fwd_level<41, false, 32>(sA, sB, sD + 1068, thr, tid); __syncwarp();
        fwd_level<24, false, 32>(sB, sA, sD + 1110, thr, tid); __syncwarp();
        fwd_level<15, true,  32>(sA, sB, sD + 1134, thr, tid); __syncwarp();
        inv_level<15, 32>(sB + 6, sD + 1134, sA + 8, tid);     __syncwarp();
        inv_level<24, 32>(sA + 8, sD + 1110, sB + 8, tid);     __syncwarp();
        inv_level<41, 32>(sB + 8, sD + 1068, sA + 8, tid);
    }
    __syncthreads();

    // ---- inverse DWT, big levels; final level streams to gmem
    inv_level<76,  NTHREADS>(sA + 8, sD + 992, sB + 8, tid); __syncthreads();
    inv_level<145, NTHREADS>(sB + 8, sD + 846, sA + 8, tid); __syncthreads();
    inv_level<284, NTHREADS>(sA + 8, sD + 562, sB + 8, tid); __syncthreads();
    inv_level<561, NTHREADS>(sB + 8, sD + 0, out + (size_t)row * N0, tid);
}

extern "C" void kernel_launch(void* const* d_in, const int* in_sizes, int n_in,
                              void* d_out, int out_size)
{
    const float* x    = (const float*)d_in[0];
    const float* rthr = (const float*)d_in[1];
    float* out        = (float*)d_out;
    wavelet_fused_kernel<<<NROWS, NTHREADS>>>(x, rthr, out);
}